// round 13
// baseline (speedup 1.0000x reference)
#include <cuda_runtime.h>
#include <math.h>

#define BB 4
#define NN 4096
#define KK 16
#define K17 17
#define EPSF 1e-12f
#define TPB 512
#define BLKQ 128              // query slots per block
#define BPB 37                // blocks per batch -> grid = 4*37 = 148 = SM count
#define SEGS 4
#define SEGN (NN / SEGS)      // 1024
#define CHUNK 64
#define BIGF 3.4e38f

// scratch: kappa values for [pass][batch][point]; pass 0 = ori, pass 1 = adv
__device__ float g_kappa[2][BB][NN];

// ---- dynamic smem layout (bytes) ----
#define OFF_TILE 0                                      // float4 [NN]           65536
#define OFF_PD   (OFF_TILE + NN * 16)                   // float [3][BLKQ][K17]  26112
#define OFF_PI   (OFF_PD + (SEGS - 1) * BLKQ * K17 * 4) // u16   [3][BLKQ][K17]  13056
#define OFF_AMD  (OFF_PI + (SEGS - 1) * BLKQ * K17 * 2) // float [SEGS*BLKQ]      2048
#define OFF_AMI  (OFF_AMD + SEGS * BLKQ * 4)            // int   [SEGS*BLKQ]      2048
#define OFF_RS   (OFF_AMI + SEGS * BLKQ * 4)            // float [SEGS*BLKQ]      2048
#define SMEM_TOTAL (OFF_RS + SEGS * BLKQ * 4)           // = 110848 (~108 KB)

__device__ __forceinline__ void insert17(float* bd, int* bi, float d, int i)
{
#pragma unroll
    for (int t = 0; t < K17; ++t) {
        if (d < bd[t]) {
            float td = bd[t]; bd[t] = d; d = td;
            int   ti = bi[t]; bi[t] = i; i = ti;
        }
    }
}

__device__ __forceinline__ void load_tile(float4* tile, const float* pc, int tid)
{
    for (int j = tid; j < NN; j += TPB) {
        float x = pc[3 * j + 0];
        float y = pc[3 * j + 1];
        float z = pc[3 * j + 2];
        tile[j] = make_float4(x, y, z, x * x + y * y + z * z);
    }
}

// Round-3 distance expression, verbatim
__device__ __forceinline__ float dref(float4 p, float ax, float ay, float az, float na)
{
    float dot = fmaf(az, p.z, fmaf(ay, p.y, ax * p.x));
    return fmaf(-2.0f, dot, na + p.w);
}

// Per-segment provable bound: 5th-smallest of 128 stride-8 samples.
// >=5 candidates/segment are <= s4 => >=20 total <= max_seg(s4) = R => d_(17) <= R.
__device__ __forceinline__ float sample_bound(
    const float4* __restrict__ tile, int segbase,
    float ax, float ay, float az, float na)
{
    float s0 = BIGF, s1 = BIGF, s2 = BIGF, s3 = BIGF, s4 = BIGF;
#pragma unroll 4
    for (int t = 0; t < 128; ++t) {
        float c = dref(tile[segbase + (t << 3)], ax, ay, az, na);
        float m;
        m = fminf(s0, c); c = fmaxf(s0, c); s0 = m;
        m = fminf(s1, c); c = fmaxf(s1, c); s1 = m;
        m = fminf(s2, c); c = fmaxf(s2, c); s2 = m;
        m = fminf(s3, c); c = fmaxf(s3, c); s3 = m;
        m = fminf(s4, c); c = fmaxf(s4, c); s4 = m;
    }
    return s4;
}

// Chunked filtered exact scan — BRANCH-FREE survivor compaction.
// Every iteration stores (d, j) to buf[c]; c advances only for survivors
// (d <= lim). Store-before-increment => c <= in-chunk iteration index, so a
// CHUNK-sized buffer can never overflow (no cap check, no fallback path, no
// divergent branch in the hot loop). Selection stays bit-identical: exactly
// the survivors (d <= lim <= R, R provably >= d_(17)) reach insert17, in
// index order, via the same strict-'<' chain as Rounds 3-12.
template <bool DO_ARGMIN>
__device__ __forceinline__ void scan_seg(
    const float4* __restrict__ tile, int segbase, float R,
    float ax, float ay, float az, float na,
    float bx, float by, float bz, float nb,
    float* bd, int* bi, float* dmin_out, int* jmin_out)
{
    float worst = bd[K17 - 1];
    float lim = fminf(R, worst);
    float dmin = BIGF; int jmin = 0;
    for (int c0 = 0; c0 < SEGN; c0 += CHUNK) {
        float2 buf[CHUNK];
        int c = 0;
#pragma unroll 4
        for (int j = c0; j < c0 + CHUNK; ++j) {
            float4 p = tile[segbase + j];
            float d = dref(p, ax, ay, az, na);
            if (DO_ARGMIN) {
                float d2 = dref(p, bx, by, bz, nb);
                if (d2 < dmin) { dmin = d2; jmin = segbase + j; }
            }
            buf[c] = make_float2(d, __int_as_float(segbase + j));
            c += (d <= lim) ? 1 : 0;
        }
        for (int t = 0; t < c; ++t) {
            float2 v = buf[t];
            if (v.x < worst) {
                insert17(bd, bi, v.x, __float_as_int(v.y));
                worst = bd[K17 - 1];
            }
        }
        lim = fminf(R, worst);
    }
    if (DO_ARGMIN) { *dmin_out = dmin; *jmin_out = jmin; }
}

// merge 3 other partial lists into (bd,bi), lists sorted ascending
__device__ __forceinline__ void merge_partials(const float* pd, const unsigned short* pi,
                                               int ql, float* bd, int* bi)
{
    float worst = bd[K17 - 1];
#pragma unroll
    for (int s = 0; s < SEGS - 1; ++s) {
        const float* qd = pd + (s * BLKQ + ql) * K17;
        const unsigned short* qi = pi + (s * BLKQ + ql) * K17;
        for (int t = 0; t < K17; ++t) {
            float d = qd[t];
            if (d >= worst) break;
            insert17(bd, bi, d, (int)qi[t]);
            worst = bd[K17 - 1];
        }
    }
}

__device__ __forceinline__ float kappa_from_topk(const float4* tile,
                                                 float ax, float ay, float az,
                                                 float nx, float ny, float nz,
                                                 const int* bi)
{
    float s = 0.0f;
#pragma unroll
    for (int t = 1; t < K17; ++t) {     // drop entry 0 (self / nearest)
        float4 p = tile[bi[t]];
        float vx = p.x - ax, vy = p.y - ay, vz = p.z - az;
        float nv = sqrtf(vx * vx + vy * vy + vz * vz);
        float inv = 1.0f / (nv + EPSF);
        s += fabsf((vx * nx + vy * ny + vz * nz) * inv);
    }
    return s * (1.0f / KK);
}

__device__ __forceinline__ void publish_partials(float* pd, unsigned short* pi,
                                                 int seg, int ql,
                                                 const float* bd, const int* bi)
{
    float* qd = pd + ((seg - 1) * BLKQ + ql) * K17;
    unsigned short* qi = pi + ((seg - 1) * BLKQ + ql) * K17;
#pragma unroll
    for (int t = 0; t < K17; ++t) { qd[t] = bd[t]; qi[t] = (unsigned short)bi[t]; }
}

// ---------------------------------------------------------------------------
// fused kernel: ori top-17 + adv argmin on the ori tile, then adv top-17.
// Grid = BB * BPB = 148 blocks; block i of a batch covers queries
// [i*NN/BPB, (i+1)*NN/BPB)  (110 or 111 queries; slots up to BLKQ=128).
// ---------------------------------------------------------------------------
__global__ __launch_bounds__(TPB, 1) void kappa_all_kernel(
    const float* __restrict__ ori, const float* __restrict__ adv,
    const float* __restrict__ nrm)
{
    extern __shared__ char smem[];
    float4* tile = (float4*)(smem + OFF_TILE);
    float*  pd   = (float*)(smem + OFF_PD);
    unsigned short* pi = (unsigned short*)(smem + OFF_PI);
    float*  amd  = (float*)(smem + OFF_AMD);
    int*    ami  = (int*)(smem + OFF_AMI);
    float*  rs   = (float*)(smem + OFF_RS);

    const int tid = threadIdx.x;
    const int ql  = tid % BLKQ;
    const int seg = tid / BLKQ;
    const int segbase = seg * SEGN;
    const int b   = blockIdx.x / BPB;
    const int blk = blockIdx.x % BPB;
    const int q0    = (blk * NN) / BPB;
    const int q1    = ((blk + 1) * NN) / BPB;
    const int count = q1 - q0;                 // 110 or 111
    const int q   = q0 + ql;
    const int qe  = (ql < count) ? q : q0;     // clamped for loads
    const bool active = (ql < count);

    const float* pco = ori + (size_t)b * NN * 3;
    const float* pca = adv + (size_t)b * NN * 3;
    const float* nr  = nrm + (size_t)b * NN * 3;

    const float ax = pco[3 * qe + 0];
    const float ay = pco[3 * qe + 1];
    const float az = pco[3 * qe + 2];
    const float na = ax * ax + ay * ay + az * az;
    const float bx = pca[3 * qe + 0];
    const float by = pca[3 * qe + 1];
    const float bz = pca[3 * qe + 2];
    const float nb = bx * bx + by * by + bz * bz;

    // ===================== phase A: ori tile =====================
    load_tile(tile, pco, tid);
    __syncthreads();

    rs[seg * BLKQ + ql] = sample_bound(tile, segbase, ax, ay, az, na);
    __syncthreads();
    float R = fmaxf(fmaxf(rs[0 * BLKQ + ql], rs[1 * BLKQ + ql]),
                    fmaxf(rs[2 * BLKQ + ql], rs[3 * BLKQ + ql]));

    float bd[K17]; int bi[K17];
#pragma unroll
    for (int t = 0; t < K17; ++t) { bd[t] = BIGF; bi[t] = 0; }

    float dmin; int jmin;
    scan_seg<true>(tile, segbase, R, ax, ay, az, na, bx, by, bz, nb,
                   bd, bi, &dmin, &jmin);

    amd[seg * BLKQ + ql] = dmin;
    ami[seg * BLKQ + ql] = jmin;
    if (seg != 0) publish_partials(pd, pi, seg, ql, bd, bi);
    __syncthreads();

    float nx = 0.f, ny = 0.f, nz = 0.f;
    if (seg == 0) {
        merge_partials(pd, pi, ql, bd, bi);
        if (active) {
            float onx = nr[3 * q + 0], ony = nr[3 * q + 1], onz = nr[3 * q + 2];
            g_kappa[0][b][q] = kappa_from_topk(tile, ax, ay, az, onx, ony, onz, bi);
        }
        // gather nearest-ori normal for the adv query (first-min across segs)
        float best = BIGF; int jm = 0;
#pragma unroll
        for (int s = 0; s < SEGS; ++s) {
            float d = amd[s * BLKQ + ql];
            if (d < best) { best = d; jm = ami[s * BLKQ + ql]; }
        }
        nx = nr[3 * jm + 0]; ny = nr[3 * jm + 1]; nz = nr[3 * jm + 2];
    }
    __syncthreads();   // everyone done reading ori tile

    // ===================== phase B: adv tile =====================
    load_tile(tile, pca, tid);
    __syncthreads();

    rs[seg * BLKQ + ql] = sample_bound(tile, segbase, bx, by, bz, nb);
    __syncthreads();
    R = fmaxf(fmaxf(rs[0 * BLKQ + ql], rs[1 * BLKQ + ql]),
              fmaxf(rs[2 * BLKQ + ql], rs[3 * BLKQ + ql]));

#pragma unroll
    for (int t = 0; t < K17; ++t) { bd[t] = BIGF; bi[t] = 0; }

    scan_seg<false>(tile, segbase, R, bx, by, bz, nb, 0.f, 0.f, 0.f, 0.f,
                    bd, bi, &dmin, &jmin);

    if (seg != 0) publish_partials(pd, pi, seg, ql, bd, bi);
    __syncthreads();

    if (seg == 0 && active) {
        merge_partials(pd, pi, ql, bd, bi);
        g_kappa[1][b][q] = kappa_from_topk(tile, bx, by, bz, nx, ny, nz, bi);
    }
}

// ---------------------------------------------------------------------------
// parallel reduce: 8 groups of 128 threads, one per (pass, batch)
// ---------------------------------------------------------------------------
__global__ __launch_bounds__(1024) void reduce_kernel(float* __restrict__ out)
{
    __shared__ double red[1024];
    __shared__ double s_std[8];
    const int tid = threadIdx.x;
    const int g = tid >> 7;
    const int l = tid & 127;
    const int p = g >> 2;
    const int b = g & 3;

    double s = 0.0;
    for (int i = l; i < NN; i += 128) s += (double)g_kappa[p][b][i];
    red[tid] = s;
    __syncthreads();
    for (int st = 64; st > 0; st >>= 1) {
        if (l < st) red[tid] += red[tid + st];
        __syncthreads();
    }
    double mean = red[g << 7] / (double)NN;
    __syncthreads();

    double s2 = 0.0;
    for (int i = l; i < NN; i += 128) {
        double dv = (double)g_kappa[p][b][i] - mean;
        s2 += dv * dv;
    }
    red[tid] = s2;
    __syncthreads();
    for (int st = 64; st > 0; st >>= 1) {
        if (l < st) red[tid] += red[tid + st];
        __syncthreads();
    }
    if (l == 0) s_std[g] = sqrt(red[tid] / (double)(NN - 1));
    __syncthreads();

    if (tid == 0) {
        double acc = 0.0;
        for (int bb = 0; bb < BB; ++bb) acc += fabs(s_std[4 + bb] - s_std[bb]);
        out[0] = (float)(acc / (double)BB);
    }
}

// ---------------------------------------------------------------------------
extern "C" void kernel_launch(void* const* d_in, const int* in_sizes, int n_in,
                              void* d_out, int out_size)
{
    const float* ori = (const float*)d_in[0];
    const float* adv = (const float*)d_in[1];
    const float* nrm = (const float*)d_in[2];
    float* out = (float*)d_out;

    cudaFuncSetAttribute(kappa_all_kernel,
                         cudaFuncAttributeMaxDynamicSharedMemorySize, SMEM_TOTAL);

    kappa_all_kernel<<<BB * BPB, TPB, SMEM_TOTAL>>>(ori, adv, nrm);
    reduce_kernel<<<1, 1024>>>(out);
}

// round 15
// speedup vs baseline: 2.5150x; 2.5150x over previous
#include <cuda_runtime.h>
#include <math.h>

#define BB 4
#define NN 4096
#define KK 16
#define K17 17
#define EPSF 1e-12f
#define TPB 512
#define BLKQ 128              // query slots per block
#define BPB 37                // blocks per batch -> grid = 4*37 = 148 = SM count
#define SEGS 4
#define SEGN (NN / SEGS)      // 1024
#define CHUNK 64
#define CCAP 16
#define NSAMP 5               // per-segment sampled minima kept
#define BIGF 3.4e38f

// scratch: kappa values for [pass][batch][point]; pass 0 = ori, pass 1 = adv
__device__ float g_kappa[2][BB][NN];

// ---- dynamic smem layout (bytes) ----
#define OFF_TILE 0                                      // float4 [NN]           65536
#define OFF_PD   (OFF_TILE + NN * 16)                   // float [3][BLKQ][K17]  26112
#define OFF_PI   (OFF_PD + (SEGS - 1) * BLKQ * K17 * 4) // u16   [3][BLKQ][K17]  13056
#define OFF_AMD  (OFF_PI + (SEGS - 1) * BLKQ * K17 * 2) // float [SEGS*BLKQ]      2048
#define OFF_AMI  (OFF_AMD + SEGS * BLKQ * 4)            // int   [SEGS*BLKQ]      2048
#define OFF_RS   (OFF_AMI + SEGS * BLKQ * 4)            // float [SEGS*NSAMP*BLKQ] 10240
#define SMEM_TOTAL (OFF_RS + SEGS * NSAMP * BLKQ * 4)   // = 119040 (~116 KB)

__device__ __forceinline__ void insert17(float* bd, int* bi, float d, int i)
{
#pragma unroll
    for (int t = 0; t < K17; ++t) {
        if (d < bd[t]) {
            float td = bd[t]; bd[t] = d; d = td;
            int   ti = bi[t]; bi[t] = i; i = ti;
        }
    }
}

__device__ __forceinline__ void load_tile(float4* tile, const float* pc, int tid)
{
    for (int j = tid; j < NN; j += TPB) {
        float x = pc[3 * j + 0];
        float y = pc[3 * j + 1];
        float z = pc[3 * j + 2];
        tile[j] = make_float4(x, y, z, x * x + y * y + z * z);
    }
}

// Round-3 distance expression, verbatim
__device__ __forceinline__ float dref(float4 p, float ax, float ay, float az, float na)
{
    float dot = fmaf(az, p.z, fmaf(ay, p.y, ax * p.x));
    return fmaf(-2.0f, dot, na + p.w);
}

// Per-segment sampling: 5 smallest of 256 stride-4 samples, published to rs.
__device__ __forceinline__ void sample_mins(
    const float4* __restrict__ tile, int segbase,
    float ax, float ay, float az, float na,
    float* rs, int seg, int ql)
{
    float s0 = BIGF, s1 = BIGF, s2 = BIGF, s3 = BIGF, s4 = BIGF;
#pragma unroll 4
    for (int t = 0; t < 256; ++t) {
        float c = dref(tile[segbase + (t << 2)], ax, ay, az, na);
        float m;
        m = fminf(s0, c); c = fmaxf(s0, c); s0 = m;
        m = fminf(s1, c); c = fmaxf(s1, c); s1 = m;
        m = fminf(s2, c); c = fmaxf(s2, c); s2 = m;
        m = fminf(s3, c); c = fmaxf(s3, c); s3 = m;
        m = fminf(s4, c); c = fmaxf(s4, c); s4 = m;
    }
    rs[(seg * NSAMP + 0) * BLKQ + ql] = s0;
    rs[(seg * NSAMP + 1) * BLKQ + ql] = s1;
    rs[(seg * NSAMP + 2) * BLKQ + ql] = s2;
    rs[(seg * NSAMP + 3) * BLKQ + ql] = s3;
    rs[(seg * NSAMP + 4) * BLKQ + ql] = s4;
}

// Pooled bound: 17th smallest (= 4th largest) of the 20 published sample
// minima for this query. >=17 pooled values <= R, each an actual candidate
// distance => d_(17) <= R. Provably filter-safe, and much tighter than
// max-of-per-seg-5th (pool rank 17 ~ global rank ~70-100 at stride 4).
__device__ __forceinline__ float pooled_bound(const float* rs, int ql)
{
    float t0 = -BIGF, t1 = -BIGF, t2 = -BIGF, t3 = -BIGF;
#pragma unroll
    for (int s = 0; s < SEGS; ++s) {
#pragma unroll
        for (int k = 0; k < NSAMP; ++k) {
            float v = rs[(s * NSAMP + k) * BLKQ + ql];
            float m;
            m = fmaxf(t0, v); v = fminf(t0, v); t0 = m;
            m = fmaxf(t1, v); v = fminf(t1, v); t1 = m;
            m = fmaxf(t2, v); v = fminf(t2, v); t2 = m;
            m = fmaxf(t3, v); t3 = m;
        }
    }
    return t3;   // 4th largest of 20 = 17th smallest
}

// Chunked filtered exact scan — Round 9 verbatim (CCAP=16 conditional-store
// L1-resident buffer, exact-insert overflow fallback; bit-identical selection).
template <bool DO_ARGMIN>
__device__ __forceinline__ void scan_seg(
    const float4* __restrict__ tile, int segbase, float R,
    float ax, float ay, float az, float na,
    float bx, float by, float bz, float nb,
    float* bd, int* bi, float* dmin_out, int* jmin_out)
{
    float worst = bd[K17 - 1];
    float lim = fminf(R, worst);
    float dmin = BIGF; int jmin = 0;
    for (int c0 = 0; c0 < SEGN; c0 += CHUNK) {
        float bufd[CCAP];
        int   bufj[CCAP];
        int c = 0;
#pragma unroll 4
        for (int j = c0; j < c0 + CHUNK; ++j) {
            float4 p = tile[segbase + j];
            float d = dref(p, ax, ay, az, na);
            if (DO_ARGMIN) {
                float d2 = dref(p, bx, by, bz, nb);
                if (d2 < dmin) { dmin = d2; jmin = segbase + j; }
            }
            if (d <= lim) {
                if (c < CCAP) { bufd[c] = d; bufj[c] = segbase + j; ++c; }
                else { insert17(bd, bi, d, segbase + j); worst = bd[K17 - 1]; }
            }
        }
        for (int t = 0; t < c; ++t) {
            float d = bufd[t];
            if (d < worst) {
                insert17(bd, bi, d, bufj[t]);
                worst = bd[K17 - 1];
            }
        }
        lim = fminf(R, worst);
    }
    if (DO_ARGMIN) { *dmin_out = dmin; *jmin_out = jmin; }
}

// merge 3 other partial lists into (bd,bi), lists sorted ascending
__device__ __forceinline__ void merge_partials(const float* pd, const unsigned short* pi,
                                               int ql, float* bd, int* bi)
{
    float worst = bd[K17 - 1];
#pragma unroll
    for (int s = 0; s < SEGS - 1; ++s) {
        const float* qd = pd + (s * BLKQ + ql) * K17;
        const unsigned short* qi = pi + (s * BLKQ + ql) * K17;
        for (int t = 0; t < K17; ++t) {
            float d = qd[t];
            if (d >= worst) break;
            insert17(bd, bi, d, (int)qi[t]);
            worst = bd[K17 - 1];
        }
    }
}

__device__ __forceinline__ float kappa_from_topk(const float4* tile,
                                                 float ax, float ay, float az,
                                                 float nx, float ny, float nz,
                                                 const int* bi)
{
    float s = 0.0f;
#pragma unroll
    for (int t = 1; t < K17; ++t) {     // drop entry 0 (self / nearest)
        float4 p = tile[bi[t]];
        float vx = p.x - ax, vy = p.y - ay, vz = p.z - az;
        float nv = sqrtf(vx * vx + vy * vy + vz * vz);
        float inv = 1.0f / (nv + EPSF);
        s += fabsf((vx * nx + vy * ny + vz * nz) * inv);
    }
    return s * (1.0f / KK);
}

__device__ __forceinline__ void publish_partials(float* pd, unsigned short* pi,
                                                 int seg, int ql,
                                                 const float* bd, const int* bi)
{
    float* qd = pd + ((seg - 1) * BLKQ + ql) * K17;
    unsigned short* qi = pi + ((seg - 1) * BLKQ + ql) * K17;
#pragma unroll
    for (int t = 0; t < K17; ++t) { qd[t] = bd[t]; qi[t] = (unsigned short)bi[t]; }
}

// ---------------------------------------------------------------------------
// fused kernel: ori top-17 + adv argmin on the ori tile, then adv top-17.
// ---------------------------------------------------------------------------
__global__ __launch_bounds__(TPB, 1) void kappa_all_kernel(
    const float* __restrict__ ori, const float* __restrict__ adv,
    const float* __restrict__ nrm)
{
    extern __shared__ char smem[];
    float4* tile = (float4*)(smem + OFF_TILE);
    float*  pd   = (float*)(smem + OFF_PD);
    unsigned short* pi = (unsigned short*)(smem + OFF_PI);
    float*  amd  = (float*)(smem + OFF_AMD);
    int*    ami  = (int*)(smem + OFF_AMI);
    float*  rs   = (float*)(smem + OFF_RS);

    const int tid = threadIdx.x;
    const int ql  = tid % BLKQ;
    const int seg = tid / BLKQ;
    const int segbase = seg * SEGN;
    const int b   = blockIdx.x / BPB;
    const int blk = blockIdx.x % BPB;
    const int q0    = (blk * NN) / BPB;
    const int q1    = ((blk + 1) * NN) / BPB;
    const int count = q1 - q0;                 // 110 or 111
    const int q   = q0 + ql;
    const int qe  = (ql < count) ? q : q0;     // clamped for loads
    const bool active = (ql < count);

    const float* pco = ori + (size_t)b * NN * 3;
    const float* pca = adv + (size_t)b * NN * 3;
    const float* nr  = nrm + (size_t)b * NN * 3;

    const float ax = pco[3 * qe + 0];
    const float ay = pco[3 * qe + 1];
    const float az = pco[3 * qe + 2];
    const float na = ax * ax + ay * ay + az * az;
    const float bx = pca[3 * qe + 0];
    const float by = pca[3 * qe + 1];
    const float bz = pca[3 * qe + 2];
    const float nb = bx * bx + by * by + bz * bz;

    // ===================== phase A: ori tile =====================
    load_tile(tile, pco, tid);
    __syncthreads();

    sample_mins(tile, segbase, ax, ay, az, na, rs, seg, ql);
    __syncthreads();
    float R = pooled_bound(rs, ql);

    float bd[K17]; int bi[K17];
#pragma unroll
    for (int t = 0; t < K17; ++t) { bd[t] = BIGF; bi[t] = 0; }

    float dmin; int jmin;
    scan_seg<true>(tile, segbase, R, ax, ay, az, na, bx, by, bz, nb,
                   bd, bi, &dmin, &jmin);

    amd[seg * BLKQ + ql] = dmin;
    ami[seg * BLKQ + ql] = jmin;
    if (seg != 0) publish_partials(pd, pi, seg, ql, bd, bi);
    __syncthreads();

    float nx = 0.f, ny = 0.f, nz = 0.f;
    if (seg == 0) {
        merge_partials(pd, pi, ql, bd, bi);
        if (active) {
            float onx = nr[3 * q + 0], ony = nr[3 * q + 1], onz = nr[3 * q + 2];
            g_kappa[0][b][q] = kappa_from_topk(tile, ax, ay, az, onx, ony, onz, bi);
        }
        // gather nearest-ori normal for the adv query (first-min across segs)
        float best = BIGF; int jm = 0;
#pragma unroll
        for (int s = 0; s < SEGS; ++s) {
            float d = amd[s * BLKQ + ql];
            if (d < best) { best = d; jm = ami[s * BLKQ + ql]; }
        }
        nx = nr[3 * jm + 0]; ny = nr[3 * jm + 1]; nz = nr[3 * jm + 2];
    }
    __syncthreads();   // everyone done reading ori tile

    // ===================== phase B: adv tile =====================
    load_tile(tile, pca, tid);
    __syncthreads();

    sample_mins(tile, segbase, bx, by, bz, nb, rs, seg, ql);
    __syncthreads();
    R = pooled_bound(rs, ql);

#pragma unroll
    for (int t = 0; t < K17; ++t) { bd[t] = BIGF; bi[t] = 0; }

    scan_seg<false>(tile, segbase, R, bx, by, bz, nb, 0.f, 0.f, 0.f, 0.f,
                    bd, bi, &dmin, &jmin);

    if (seg != 0) publish_partials(pd, pi, seg, ql, bd, bi);
    __syncthreads();

    if (seg == 0 && active) {
        merge_partials(pd, pi, ql, bd, bi);
        g_kappa[1][b][q] = kappa_from_topk(tile, bx, by, bz, nx, ny, nz, bi);
    }
}

// ---------------------------------------------------------------------------
// parallel reduce: 8 groups of 128 threads, one per (pass, batch)
// ---------------------------------------------------------------------------
__global__ __launch_bounds__(1024) void reduce_kernel(float* __restrict__ out)
{
    __shared__ double red[1024];
    __shared__ double s_std[8];
    const int tid = threadIdx.x;
    const int g = tid >> 7;
    const int l = tid & 127;
    const int p = g >> 2;
    const int b = g & 3;

    double s = 0.0;
    for (int i = l; i < NN; i += 128) s += (double)g_kappa[p][b][i];
    red[tid] = s;
    __syncthreads();
    for (int st = 64; st > 0; st >>= 1) {
        if (l < st) red[tid] += red[tid + st];
        __syncthreads();
    }
    double mean = red[g << 7] / (double)NN;
    __syncthreads();

    double s2 = 0.0;
    for (int i = l; i < NN; i += 128) {
        double dv = (double)g_kappa[p][b][i] - mean;
        s2 += dv * dv;
    }
    red[tid] = s2;
    __syncthreads();
    for (int st = 64; st > 0; st >>= 1) {
        if (l < st) red[tid] += red[tid + st];
        __syncthreads();
    }
    if (l == 0) s_std[g] = sqrt(red[tid] / (double)(NN - 1));
    __syncthreads();

    if (tid == 0) {
        double acc = 0.0;
        for (int bb = 0; bb < BB; ++bb) acc += fabs(s_std[4 + bb] - s_std[bb]);
        out[0] = (float)(acc / (double)BB);
    }
}

// ---------------------------------------------------------------------------
extern "C" void kernel_launch(void* const* d_in, const int* in_sizes, int n_in,
                              void* d_out, int out_size)
{
    const float* ori = (const float*)d_in[0];
    const float* adv = (const float*)d_in[1];
    const float* nrm = (const float*)d_in[2];
    float* out = (float*)d_out;

    cudaFuncSetAttribute(kappa_all_kernel,
                         cudaFuncAttributeMaxDynamicSharedMemorySize, SMEM_TOTAL);

    kappa_all_kernel<<<BB * BPB, TPB, SMEM_TOTAL>>>(ori, adv, nrm);
    reduce_kernel<<<1, 1024>>>(out);
}

// round 16
// speedup vs baseline: 2.6794x; 1.0654x over previous
#include <cuda_runtime.h>
#include <math.h>

#define BB 4
#define NN 4096
#define KK 16
#define K17 17
#define EPSF 1e-12f
#define TPB 640
#define BLKQ 128              // query slots per block
#define BPB 37                // blocks per batch -> grid = 4*37 = 148 = SM count
#define SEGS 5
#define CHUNK 64
#define CCAP 12
#define NSAMP 5               // per-segment sampled minima kept
#define SSAMP 204             // stride-4 samples per segment (4*204=816 <= min seg 819)
#define BIGF 3.4e38f

// scratch: kappa values for [pass][batch][point]; pass 0 = ori, pass 1 = adv
__device__ float g_kappa[2][BB][NN];

// ---- dynamic smem layout (bytes) ----
#define OFF_TILE 0                                      // float4 [NN]            65536
#define OFF_PD   (OFF_TILE + NN * 16)                   // float [4][BLKQ][K17]   34816
#define OFF_PI   (OFF_PD + (SEGS - 1) * BLKQ * K17 * 4) // u16   [4][BLKQ][K17]   17408
#define OFF_AMD  (OFF_PI + (SEGS - 1) * BLKQ * K17 * 2) // float [SEGS*BLKQ]       2560
#define OFF_AMI  (OFF_AMD + SEGS * BLKQ * 4)            // int   [SEGS*BLKQ]       2560
#define OFF_RS   (OFF_AMI + SEGS * BLKQ * 4)            // float [SEGS*NSAMP*BLKQ] 12800
#define SMEM_TOTAL (OFF_RS + SEGS * NSAMP * BLKQ * 4)   // = 135680 (~132.5 KB)

__device__ __forceinline__ void insert17(float* bd, int* bi, float d, int i)
{
#pragma unroll
    for (int t = 0; t < K17; ++t) {
        if (d < bd[t]) {
            float td = bd[t]; bd[t] = d; d = td;
            int   ti = bi[t]; bi[t] = i; i = ti;
        }
    }
}

__device__ __forceinline__ void load_tile(float4* tile, const float* pc, int tid)
{
    for (int j = tid; j < NN; j += TPB) {
        float x = pc[3 * j + 0];
        float y = pc[3 * j + 1];
        float z = pc[3 * j + 2];
        tile[j] = make_float4(x, y, z, x * x + y * y + z * z);
    }
}

// Round-3 distance expression, verbatim
__device__ __forceinline__ float dref(float4 p, float ax, float ay, float az, float na)
{
    float dot = fmaf(az, p.z, fmaf(ay, p.y, ax * p.x));
    return fmaf(-2.0f, dot, na + p.w);
}

// Per-segment sampling: 5 smallest of 204 stride-4 samples, published to rs.
__device__ __forceinline__ void sample_mins(
    const float4* __restrict__ tile, int segbase,
    float ax, float ay, float az, float na,
    float* rs, int seg, int ql)
{
    float s0 = BIGF, s1 = BIGF, s2 = BIGF, s3 = BIGF, s4 = BIGF;
#pragma unroll 4
    for (int t = 0; t < SSAMP; ++t) {
        float c = dref(tile[segbase + (t << 2)], ax, ay, az, na);
        float m;
        m = fminf(s0, c); c = fmaxf(s0, c); s0 = m;
        m = fminf(s1, c); c = fmaxf(s1, c); s1 = m;
        m = fminf(s2, c); c = fmaxf(s2, c); s2 = m;
        m = fminf(s3, c); c = fmaxf(s3, c); s3 = m;
        m = fminf(s4, c); c = fmaxf(s4, c); s4 = m;
    }
    rs[(seg * NSAMP + 0) * BLKQ + ql] = s0;
    rs[(seg * NSAMP + 1) * BLKQ + ql] = s1;
    rs[(seg * NSAMP + 2) * BLKQ + ql] = s2;
    rs[(seg * NSAMP + 3) * BLKQ + ql] = s3;
    rs[(seg * NSAMP + 4) * BLKQ + ql] = s4;
}

// Pooled bound: 17th smallest (= 9th largest) of the 25 published sample
// minima for this query. >=17 pooled values <= R, each an actual candidate
// distance => d_(17) <= R. Provably filter-safe.
__device__ __forceinline__ float pooled_bound(const float* rs, int ql)
{
    float t0 = -BIGF, t1 = -BIGF, t2 = -BIGF, t3 = -BIGF, t4 = -BIGF;
    float t5 = -BIGF, t6 = -BIGF, t7 = -BIGF, t8 = -BIGF;
#pragma unroll
    for (int k = 0; k < SEGS * NSAMP; ++k) {
        float v = rs[k * BLKQ + ql];
        float m;
        m = fmaxf(t0, v); v = fminf(t0, v); t0 = m;
        m = fmaxf(t1, v); v = fminf(t1, v); t1 = m;
        m = fmaxf(t2, v); v = fminf(t2, v); t2 = m;
        m = fmaxf(t3, v); v = fminf(t3, v); t3 = m;
        m = fmaxf(t4, v); v = fminf(t4, v); t4 = m;
        m = fmaxf(t5, v); v = fminf(t5, v); t5 = m;
        m = fmaxf(t6, v); v = fminf(t6, v); t6 = m;
        m = fmaxf(t7, v); v = fminf(t7, v); t7 = m;
        m = fmaxf(t8, v); t8 = m;
    }
    return t8;   // 9th largest of 25 = 17th smallest
}

// Chunked filtered exact scan (CCAP conditional-store L1-resident buffer,
// exact-insert overflow fallback; bit-identical selection). Segment bounds
// [segbase, segend) may be uneven (819 or 820).
template <bool DO_ARGMIN>
__device__ __forceinline__ void scan_seg(
    const float4* __restrict__ tile, int segbase, int segend, float R,
    float ax, float ay, float az, float na,
    float bx, float by, float bz, float nb,
    float* bd, int* bi, float* dmin_out, int* jmin_out)
{
    float worst = bd[K17 - 1];
    float lim = fminf(R, worst);
    float dmin = BIGF; int jmin = 0;
    for (int c0 = segbase; c0 < segend; c0 += CHUNK) {
        const int cend = (c0 + CHUNK < segend) ? c0 + CHUNK : segend;
        float bufd[CCAP];
        int   bufj[CCAP];
        int c = 0;
#pragma unroll 4
        for (int j = c0; j < cend; ++j) {
            float4 p = tile[j];
            float d = dref(p, ax, ay, az, na);
            if (DO_ARGMIN) {
                float d2 = dref(p, bx, by, bz, nb);
                if (d2 < dmin) { dmin = d2; jmin = j; }
            }
            if (d <= lim) {
                if (c < CCAP) { bufd[c] = d; bufj[c] = j; ++c; }
                else { insert17(bd, bi, d, j); worst = bd[K17 - 1]; }
            }
        }
        for (int t = 0; t < c; ++t) {
            float d = bufd[t];
            if (d < worst) {
                insert17(bd, bi, d, bufj[t]);
                worst = bd[K17 - 1];
            }
        }
        lim = fminf(R, worst);
    }
    if (DO_ARGMIN) { *dmin_out = dmin; *jmin_out = jmin; }
}

// merge 4 other partial lists into (bd,bi), lists sorted ascending
__device__ __forceinline__ void merge_partials(const float* pd, const unsigned short* pi,
                                               int ql, float* bd, int* bi)
{
    float worst = bd[K17 - 1];
#pragma unroll
    for (int s = 0; s < SEGS - 1; ++s) {
        const float* qd = pd + (s * BLKQ + ql) * K17;
        const unsigned short* qi = pi + (s * BLKQ + ql) * K17;
        for (int t = 0; t < K17; ++t) {
            float d = qd[t];
            if (d >= worst) break;
            insert17(bd, bi, d, (int)qi[t]);
            worst = bd[K17 - 1];
        }
    }
}

__device__ __forceinline__ float kappa_from_topk(const float4* tile,
                                                 float ax, float ay, float az,
                                                 float nx, float ny, float nz,
                                                 const int* bi)
{
    float s = 0.0f;
#pragma unroll
    for (int t = 1; t < K17; ++t) {     // drop entry 0 (self / nearest)
        float4 p = tile[bi[t]];
        float vx = p.x - ax, vy = p.y - ay, vz = p.z - az;
        float nv = sqrtf(vx * vx + vy * vy + vz * vz);
        float inv = 1.0f / (nv + EPSF);
        s += fabsf((vx * nx + vy * ny + vz * nz) * inv);
    }
    return s * (1.0f / KK);
}

__device__ __forceinline__ void publish_partials(float* pd, unsigned short* pi,
                                                 int seg, int ql,
                                                 const float* bd, const int* bi)
{
    float* qd = pd + ((seg - 1) * BLKQ + ql) * K17;
    unsigned short* qi = pi + ((seg - 1) * BLKQ + ql) * K17;
#pragma unroll
    for (int t = 0; t < K17; ++t) { qd[t] = bd[t]; qi[t] = (unsigned short)bi[t]; }
}

// ---------------------------------------------------------------------------
// fused kernel: ori top-17 + adv argmin on the ori tile, then adv top-17.
// 5 segment-threads per query (segments 819/819/819/819/820).
// ---------------------------------------------------------------------------
__global__ __launch_bounds__(TPB, 1) void kappa_all_kernel(
    const float* __restrict__ ori, const float* __restrict__ adv,
    const float* __restrict__ nrm)
{
    extern __shared__ char smem[];
    float4* tile = (float4*)(smem + OFF_TILE);
    float*  pd   = (float*)(smem + OFF_PD);
    unsigned short* pi = (unsigned short*)(smem + OFF_PI);
    float*  amd  = (float*)(smem + OFF_AMD);
    int*    ami  = (int*)(smem + OFF_AMI);
    float*  rs   = (float*)(smem + OFF_RS);

    const int tid = threadIdx.x;
    const int ql  = tid % BLKQ;
    const int seg = tid / BLKQ;                // 0..4 (uniform per warp)
    const int segbase = (seg * NN) / SEGS;
    const int segend  = ((seg + 1) * NN) / SEGS;
    const int b   = blockIdx.x / BPB;
    const int blk = blockIdx.x % BPB;
    const int q0    = (blk * NN) / BPB;
    const int q1    = ((blk + 1) * NN) / BPB;
    const int count = q1 - q0;                 // 110 or 111
    const int q   = q0 + ql;
    const int qe  = (ql < count) ? q : q0;     // clamped for loads
    const bool active = (ql < count);

    const float* pco = ori + (size_t)b * NN * 3;
    const float* pca = adv + (size_t)b * NN * 3;
    const float* nr  = nrm + (size_t)b * NN * 3;

    const float ax = pco[3 * qe + 0];
    const float ay = pco[3 * qe + 1];
    const float az = pco[3 * qe + 2];
    const float na = ax * ax + ay * ay + az * az;
    const float bx = pca[3 * qe + 0];
    const float by = pca[3 * qe + 1];
    const float bz = pca[3 * qe + 2];
    const float nb = bx * bx + by * by + bz * bz;

    // ===================== phase A: ori tile =====================
    load_tile(tile, pco, tid);
    __syncthreads();

    sample_mins(tile, segbase, ax, ay, az, na, rs, seg, ql);
    __syncthreads();
    float R = pooled_bound(rs, ql);

    float bd[K17]; int bi[K17];
#pragma unroll
    for (int t = 0; t < K17; ++t) { bd[t] = BIGF; bi[t] = 0; }

    float dmin; int jmin;
    scan_seg<true>(tile, segbase, segend, R, ax, ay, az, na, bx, by, bz, nb,
                   bd, bi, &dmin, &jmin);

    amd[seg * BLKQ + ql] = dmin;
    ami[seg * BLKQ + ql] = jmin;
    if (seg != 0) publish_partials(pd, pi, seg, ql, bd, bi);
    __syncthreads();

    float nx = 0.f, ny = 0.f, nz = 0.f;
    if (seg == 0) {
        merge_partials(pd, pi, ql, bd, bi);
        if (active) {
            float onx = nr[3 * q + 0], ony = nr[3 * q + 1], onz = nr[3 * q + 2];
            g_kappa[0][b][q] = kappa_from_topk(tile, ax, ay, az, onx, ony, onz, bi);
        }
        // gather nearest-ori normal for the adv query (first-min across segs)
        float best = BIGF; int jm = 0;
#pragma unroll
        for (int s = 0; s < SEGS; ++s) {
            float d = amd[s * BLKQ + ql];
            if (d < best) { best = d; jm = ami[s * BLKQ + ql]; }
        }
        nx = nr[3 * jm + 0]; ny = nr[3 * jm + 1]; nz = nr[3 * jm + 2];
    }
    __syncthreads();   // everyone done reading ori tile

    // ===================== phase B: adv tile =====================
    load_tile(tile, pca, tid);
    __syncthreads();

    sample_mins(tile, segbase, bx, by, bz, nb, rs, seg, ql);
    __syncthreads();
    R = pooled_bound(rs, ql);

#pragma unroll
    for (int t = 0; t < K17; ++t) { bd[t] = BIGF; bi[t] = 0; }

    scan_seg<false>(tile, segbase, segend, R, bx, by, bz, nb, 0.f, 0.f, 0.f, 0.f,
                    bd, bi, &dmin, &jmin);

    if (seg != 0) publish_partials(pd, pi, seg, ql, bd, bi);
    __syncthreads();

    if (seg == 0 && active) {
        merge_partials(pd, pi, ql, bd, bi);
        g_kappa[1][b][q] = kappa_from_topk(tile, bx, by, bz, nx, ny, nz, bi);
    }
}

// ---------------------------------------------------------------------------
// parallel reduce: 8 groups of 128 threads, one per (pass, batch)
// ---------------------------------------------------------------------------
__global__ __launch_bounds__(1024) void reduce_kernel(float* __restrict__ out)
{
    __shared__ double red[1024];
    __shared__ double s_std[8];
    const int tid = threadIdx.x;
    const int g = tid >> 7;
    const int l = tid & 127;
    const int p = g >> 2;
    const int b = g & 3;

    double s = 0.0;
    for (int i = l; i < NN; i += 128) s += (double)g_kappa[p][b][i];
    red[tid] = s;
    __syncthreads();
    for (int st = 64; st > 0; st >>= 1) {
        if (l < st) red[tid] += red[tid + st];
        __syncthreads();
    }
    double mean = red[g << 7] / (double)NN;
    __syncthreads();

    double s2 = 0.0;
    for (int i = l; i < NN; i += 128) {
        double dv = (double)g_kappa[p][b][i] - mean;
        s2 += dv * dv;
    }
    red[tid] = s2;
    __syncthreads();
    for (int st = 64; st > 0; st >>= 1) {
        if (l < st) red[tid] += red[tid + st];
        __syncthreads();
    }
    if (l == 0) s_std[g] = sqrt(red[tid] / (double)(NN - 1));
    __syncthreads();

    if (tid == 0) {
        double acc = 0.0;
        for (int bb = 0; bb < BB; ++bb) acc += fabs(s_std[4 + bb] - s_std[bb]);
        out[0] = (float)(acc / (double)BB);
    }
}

// ---------------------------------------------------------------------------
extern "C" void kernel_launch(void* const* d_in, const int* in_sizes, int n_in,
                              void* d_out, int out_size)
{
    const float* ori = (const float*)d_in[0];
    const float* adv = (const float*)d_in[1];
    const float* nrm = (const float*)d_in[2];
    float* out = (float*)d_out;

    cudaFuncSetAttribute(kappa_all_kernel,
                         cudaFuncAttributeMaxDynamicSharedMemorySize, SMEM_TOTAL);

    kappa_all_kernel<<<BB * BPB, TPB, SMEM_TOTAL>>>(ori, adv, nrm);
    reduce_kernel<<<1, 1024>>>(out);
}